// round 2
// baseline (speedup 1.0000x reference)
#include <cuda_runtime.h>

// ----------------------------------------------------------------------------
// SigNet: depth-4 path signature (B=128, S=1024, C=8) + linear head (256).
//
// Pipeline (all graph-capturable, no allocations):
//   1. sig_chunk_kernel  : 128*16 blocks; each computes the signature of a
//                          64-step chunk from zero. Thread t owns (a,b,c)=t;
//                          sig4[abc][0..7] in 4 packed f32x2 regs, sig3 in a
//                          reg, and A1[a]/A2[ab] replicated per-thread so the
//                          inner loop has NO barriers and no shared writes.
//   2. sig_combine_kernel: 128 blocks, Chen-combine the 16 chunk signatures.
//   3. gemm_part_kernel  : split-k GEMM  y_part = sig @ W^T   (deterministic)
//   4. reduce_kernel     : sum k-partials + bias -> out
// ----------------------------------------------------------------------------

#define BB      128
#define SS      1024
#define CIN     7
#define NCHUNK  16
#define CL      64          // SS / NCHUNK
#define SIGCH   4680        // 8 + 64 + 512 + 4096
#define OFF2    8
#define OFF3    72
#define OFF4    584
#define DOUT    256
#define KSPLIT  24          // 24 * 195 = 4680 exactly

__device__ float g_csig[(size_t)BB * NCHUNK * SIGCH];   // ~38 MB chunk sigs
__device__ float g_sig[(size_t)BB * SIGCH];             // combined sigs
__device__ float g_part[(size_t)KSPLIT * BB * DOUT];    // gemm partials

// ---------------------------------------------------------------------------
// Kernel 1: chunk signature scan (barrier-free inner loop, f32x2 level-4).
//
// Per step (increment v, 8 channels):
//   K      = s3 + A2*(vc/2) + (A1 + va/4)*(vb*vc)/6
//   s4[d] += v[d]*K                      (4 x fma.rn.f32x2)
//   s3    += A2*vc + (A1 + va/3)*(vb*vc)/2
//   A2    += (A1 + va/2)*vb
//   A1    += va
// ---------------------------------------------------------------------------
__global__ __launch_bounds__(512, 2) void sig_chunk_kernel(const float* __restrict__ inp)
{
    const int blk = blockIdx.x;
    const int b   = blk >> 4;          // / NCHUNK
    const int ch  = blk & (NCHUNK - 1);
    const int t   = threadIdx.x;

    __shared__ __align__(16) float vbuf[CL * 8];   // increments, 8 ch per step

    // --- preload increments into shared (coalesced) ---
    if (t < CL * CIN) {                 // 448 threads: data channels
        int s_ = t / CIN, c_ = t % CIN;
        int g  = ch * CL + s_;
        float x  = inp[(b * SS + g) * CIN + c_];
        float xp = (g == 0) ? 0.0f : inp[(b * SS + g - 1) * CIN + c_];
        vbuf[s_ * 8 + c_ + 1] = x - xp;
    } else {                            // 64 threads: time channel
        int s_ = t - CL * CIN;          // 0..63
        vbuf[s_ * 8] = (ch == 0 && s_ == 0) ? 0.0f : (1.0f / 1023.0f);
    }

    const int a  = t >> 6;
    const int bq = (t >> 3) & 7;
    const int cq = t & 7;

    unsigned long long s4p0 = 0ull, s4p1 = 0ull, s4p2 = 0ull, s4p3 = 0ull;
    float s3 = 0.0f;
    float A1 = 0.0f;                    // running sig1[a]   (replicated)
    float A2 = 0.0f;                    // running sig2[ab]  (replicated)

    __syncthreads();

    #pragma unroll 4
    for (int s = 0; s < CL; s++) {
        const float* vp = &vbuf[s * 8];
        const unsigned long long* vp64 = (const unsigned long long*)vp;
        float va = vp[a];
        float vb = vp[bq];
        float vc = vp[cq];
        unsigned long long v0 = vp64[0];
        unsigned long long v1 = vp64[1];
        unsigned long long v2 = vp64[2];
        unsigned long long v3 = vp64[3];

        float tt = vb * vc;
        float K  = fmaf(A2, 0.5f * vc, s3);
        K        = fmaf(fmaf(0.25f, va, A1), (1.0f / 6.0f) * tt, K);

        unsigned long long K2;
        asm("mov.b64 %0, {%1, %1};" : "=l"(K2) : "f"(K));
        asm("fma.rn.f32x2 %0, %1, %2, %0;" : "+l"(s4p0) : "l"(v0), "l"(K2));
        asm("fma.rn.f32x2 %0, %1, %2, %0;" : "+l"(s4p1) : "l"(v1), "l"(K2));
        asm("fma.rn.f32x2 %0, %1, %2, %0;" : "+l"(s4p2) : "l"(v2), "l"(K2));
        asm("fma.rn.f32x2 %0, %1, %2, %0;" : "+l"(s4p3) : "l"(v3), "l"(K2));

        s3 = fmaf(A2, vc, s3);
        s3 = fmaf(fmaf(1.0f / 3.0f, va, A1), 0.5f * tt, s3);
        A2 = fmaf(fmaf(0.5f, va, A1), vb, A2);
        A1 += va;
    }

    // write chunk signature: [L1 | L2 | L3 | L4]
    float* out = &g_csig[(size_t)(b * NCHUNK + ch) * SIGCH];
    if ((t & 63) == 0) out[a] = A1;                 // 8 writers, one per a
    if ((t & 7)  == 0) out[OFF2 + (t >> 3)] = A2;   // 64 writers, one per ab
    out[OFF3 + t] = s3;
    unsigned long long* o64 = (unsigned long long*)(out + OFF4 + t * 8);
    o64[0] = s4p0; o64[1] = s4p1; o64[2] = s4p2; o64[3] = s4p3;
}

// ---------------------------------------------------------------------------
// Kernel 2: Chen-combine the NCHUNK chunk signatures (left-to-right).
// C_k = A_k + B_k + sum_{i+j=k} A_i (x) B_j  (A = running, B = next chunk)
// ---------------------------------------------------------------------------
__global__ __launch_bounds__(512) void sig_combine_kernel()
{
    const int b = blockIdx.x;
    const int t = threadIdx.x;
    __shared__ float R[SIGCH];
    __shared__ float X[SIGCH];

    const float* src = &g_csig[(size_t)b * NCHUNK * SIGCH];
    for (int i = t; i < SIGCH; i += 512) R[i] = src[i];

    const int a  = t >> 6;
    const int bq = (t >> 3) & 7;
    const int cq = t & 7;
    const int ab = t >> 3;

    for (int cidx = 1; cidx < NCHUNK; cidx++) {
        __syncthreads();
        const float* xs = src + (size_t)cidx * SIGCH;
        for (int i = t; i < SIGCH; i += 512) X[i] = xs[i];
        __syncthreads();

        float r1 = R[a];
        float r2 = R[OFF2 + ab];
        float r3 = R[OFF3 + t];

        // level 4 (each thread owns 8 entries) + level 3 (owns 1)
        #pragma unroll
        for (int d = 0; d < 8; d++) {
            float acc = R[OFF4 + t * 8 + d] + X[OFF4 + t * 8 + d];
            acc = fmaf(r1, X[OFF3 + (bq * 8 + cq) * 8 + d], acc);
            acc = fmaf(r2, X[OFF2 + cq * 8 + d], acc);
            acc = fmaf(r3, X[d], acc);
            R[OFF4 + t * 8 + d] = acc;
        }
        float acc3 = r3 + X[OFF3 + t];
        acc3 = fmaf(r1, X[OFF2 + bq * 8 + cq], acc3);
        acc3 = fmaf(r2, X[cq], acc3);
        R[OFF3 + t] = acc3;
        __syncthreads();

        if (t < 64) {   // level 2 (reads old R1)
            float acc2 = R[OFF2 + t] + X[OFF2 + t];
            acc2 = fmaf(R[t >> 3], X[t & 7], acc2);
            R[OFF2 + t] = acc2;
        }
        __syncthreads();

        if (t < 8) R[t] += X[t];   // level 1
    }
    __syncthreads();

    float* dst = &g_sig[(size_t)b * SIGCH];
    for (int i = t; i < SIGCH; i += 512) dst[i] = R[i];
}

// ---------------------------------------------------------------------------
// Kernel 3: split-k GEMM partials: g_part[kid] += sig[:, kchunk] @ W[:, kchunk]^T
// grid (8 out-tiles of 32, KSPLIT k-chunks of 195). Deterministic (no atomics).
// ---------------------------------------------------------------------------
__global__ __launch_bounds__(256) void gemm_part_kernel(const float* __restrict__ W)
{
    const int otile = blockIdx.x;           // 0..7
    const int kid   = blockIdx.y;           // 0..KSPLIT-1
    const int KC    = SIGCH / KSPLIT;       // 195
    const int kbeg  = kid * KC;
    const int kend  = kbeg + KC;

    __shared__ float Ws[32][33];
    __shared__ float Sg[BB][33];

    const int tid = threadIdx.x;
    const int ox  = tid & 7;                // 8 out-groups of 4
    const int by  = tid >> 3;               // 32 batch-groups of 4

    float acc[4][4];
    #pragma unroll
    for (int i = 0; i < 4; i++)
        #pragma unroll
        for (int j = 0; j < 4; j++) acc[i][j] = 0.0f;

    for (int k0 = kbeg; k0 < kend; k0 += 32) {
        for (int i = tid; i < 32 * 32; i += 256) {
            int o = i >> 5, kk = i & 31;
            int k = k0 + kk;
            Ws[o][kk] = (k < kend) ? W[(otile * 32 + o) * SIGCH + k] : 0.0f;
        }
        for (int i = tid; i < BB * 32; i += 256) {
            int bb2 = i >> 5, kk = i & 31;
            int k = k0 + kk;
            Sg[bb2][kk] = (k < kend) ? g_sig[(size_t)bb2 * SIGCH + k] : 0.0f;
        }
        __syncthreads();
        #pragma unroll 8
        for (int kk = 0; kk < 32; kk++) {
            float wv[4], sv[4];
            #pragma unroll
            for (int j = 0; j < 4; j++) wv[j] = Ws[ox * 4 + j][kk];
            #pragma unroll
            for (int i = 0; i < 4; i++) sv[i] = Sg[by * 4 + i][kk];
            #pragma unroll
            for (int i = 0; i < 4; i++)
                #pragma unroll
                for (int j = 0; j < 4; j++)
                    acc[i][j] = fmaf(sv[i], wv[j], acc[i][j]);
        }
        __syncthreads();
    }

    float* dst = &g_part[(size_t)kid * BB * DOUT];
    #pragma unroll
    for (int i = 0; i < 4; i++)
        #pragma unroll
        for (int j = 0; j < 4; j++)
            dst[(by * 4 + i) * DOUT + otile * 32 + ox * 4 + j] = acc[i][j];
}

// ---------------------------------------------------------------------------
// Kernel 4: reduce k-partials + bias -> out  (deterministic fixed order)
// ---------------------------------------------------------------------------
__global__ __launch_bounds__(256) void reduce_kernel(const float* __restrict__ bias,
                                                     float* __restrict__ out)
{
    int i = blockIdx.x * 256 + threadIdx.x;     // < 32768
    int o = i & (DOUT - 1);
    float acc = bias[o];
    #pragma unroll
    for (int k = 0; k < KSPLIT; k++)
        acc += g_part[(size_t)k * BB * DOUT + i];
    out[i] = acc;
}

// ---------------------------------------------------------------------------
extern "C" void kernel_launch(void* const* d_in, const int* in_sizes, int n_in,
                              void* d_out, int out_size)
{
    const float* inp  = (const float*)d_in[0];   // (128, 1024, 7)
    const float* W    = (const float*)d_in[1];   // (256, 4680)
    const float* bias = (const float*)d_in[2];   // (256,)
    float* out        = (float*)d_out;           // (128, 256)
    (void)in_sizes; (void)n_in; (void)out_size;

    sig_chunk_kernel<<<BB * NCHUNK, 512>>>(inp);
    sig_combine_kernel<<<BB, 512>>>();
    dim3 gg(8, KSPLIT);
    gemm_part_kernel<<<gg, 256>>>(W);
    reduce_kernel<<<(BB * DOUT) / 256, 256>>>(bias, out);
}